// round 2
// baseline (speedup 1.0000x reference)
#include <cuda_runtime.h>
#include <math.h>

// Problem constants (fixed shapes from setup_inputs)
#define BB    8
#define HIDC  64
#define NLAY  4
#define TT    19        // in_len + out_len - 1
#define INLEN 10
#define NPX   1024      // 32*32
#define LS    (BB*HIDC*NPX)   // 524288 floats per (B,64,32,32) tensor

// ---------------- scratch (device globals; no allocation at runtime) ----------------
__device__ float g_xp[INLEN*LS];     // patched input (t,b,64,32,32)
__device__ float g_h[NLAY*LS];
__device__ float g_c[NLAY*LS];
__device__ float g_m[LS];
__device__ float g_mem[2*LS];        // (b,128,32,32)
__device__ float g_xc[7*LS];         // (b,448,32,32)
__device__ float g_hc[4*LS];         // (b,256,32,32)
__device__ float g_mc[3*LS];         // (b,192,32,32)
__device__ float g_oc[LS];
__device__ float g_lc[LS];
__device__ float g_outs[TT*LS];      // (t,b,64,32,32)

__device__ __forceinline__ float sigf(float v) { return 1.0f / (1.0f + expf(-v)); }

// =====================================================================
// Generic direct 3x3 SAME conv over a 32x32 image, NCHW.
// Block: 128 threads, covers (32/SP rows) x 32 cols x 16 out-channels.
// Thread tile: PPT pixels x 8 channels in registers.
// =====================================================================
template<int CI, int SP, int EPI>
__device__ __forceinline__ void conv_body(
    const float* __restrict__ in,    // (CI,32,32) image base
    const float* __restrict__ w,     // (CO,CI,3,3) base (co0 applied inside)
    const float* __restrict__ bias,  // (CO)
    float* __restrict__ out,         // EPI=0: (CO,32,32) image base; EPI=1: (256,256) output image base
    int co0, int sp)
{
    constexpr int ROWS = 32 / SP;
    constexpr int HR   = ROWS + 2;
    constexpr int PPT  = (ROWS * 32) / 64;   // 8 for SP=2, 4 for SP=4
    __shared__ float s_in[8][HR * 34];
    __shared__ float s_w[16][8 * 9];

    const int tid  = threadIdx.x;
    const int cob  = (tid >> 6) << 3;   // 0 or 8
    const int pxg  = tid & 63;
    const int lc   = pxg & 31;
    const int lr0  = pxg >> 5;          // 0 or 1
    const int row0 = sp * ROWS;

    float bv[8];
#pragma unroll
    for (int c2 = 0; c2 < 8; c2++) bv[c2] = bias[co0 + cob + c2];
    float acc[PPT][8];
#pragma unroll
    for (int p = 0; p < PPT; p++)
#pragma unroll
        for (int c2 = 0; c2 < 8; c2++) acc[p][c2] = bv[c2];

    for (int ci0 = 0; ci0 < CI; ci0 += 8) {
        // stage input chunk with halo (zero-padded)
        for (int idx = tid; idx < 8 * HR * 34; idx += 128) {
            int ci  = idx / (HR * 34);
            int rem = idx - ci * (HR * 34);
            int r   = rem / 34;
            int cc2 = rem - r * 34;
            int gr = row0 + r - 1, gc = cc2 - 1;
            float v = 0.f;
            if ((unsigned)gr < 32u && (unsigned)gc < 32u)
                v = in[(ci0 + ci) * NPX + gr * 32 + gc];
            s_in[ci][rem] = v;
        }
        // stage weights: 16co x 8ci x 9
        for (int idx = tid; idx < 16 * 72; idx += 128) {
            int c2  = idx / 72;
            int rem = idx - c2 * 72;      // ci*9+tap within chunk
            s_w[c2][rem] = w[(co0 + c2) * CI * 9 + ci0 * 9 + rem];
        }
        __syncthreads();

#pragma unroll 1
        for (int ci = 0; ci < 8; ci++) {
#pragma unroll
            for (int dy = 0; dy < 3; dy++) {
#pragma unroll
                for (int dx = 0; dx < 3; dx++) {
                    float wv[8];
#pragma unroll
                    for (int c2 = 0; c2 < 8; c2++)
                        wv[c2] = s_w[cob + c2][ci * 9 + dy * 3 + dx];
#pragma unroll
                    for (int p = 0; p < PPT; p++) {
                        float iv = s_in[ci][(lr0 + 2 * p + dy) * 34 + lc + dx];
#pragma unroll
                        for (int c2 = 0; c2 < 8; c2++)
                            acc[p][c2] = fmaf(iv, wv[c2], acc[p][c2]);
                    }
                }
            }
        }
        __syncthreads();
    }

    if (EPI == 0) {
#pragma unroll
        for (int p = 0; p < PPT; p++) {
            int gpx = (row0 + lr0 + 2 * p) * 32 + lc;
#pragma unroll
            for (int c2 = 0; c2 < 8; c2++)
                out[(co0 + cob + c2) * NPX + gpx] = acc[p][c2];
        }
    } else {
        // decoder: sigmoid + depth-to-space 8x8 into (256,256) image
#pragma unroll
        for (int p = 0; p < PPT; p++) {
            int gr = row0 + lr0 + 2 * p;   // patch row i
#pragma unroll
            for (int c2 = 0; c2 < 8; c2++) {
                int co = co0 + cob + c2;
                out[((co >> 3) * 32 + gr) * 256 + ((co & 7) << 5) + lc] =
                    sigf(acc[p][c2]);
            }
        }
    }
}

// ---- fused xc/hc/mc conv: grid = B * 56 groups * 2 spatial = 896 blocks ----
__global__ __launch_bounds__(128) void conv_xhm_k(
    const float* __restrict__ xin, const float* __restrict__ hin, const float* __restrict__ minb,
    const float* __restrict__ wx, const float* __restrict__ bx, float* __restrict__ xc,
    const float* __restrict__ wh, const float* __restrict__ bh, float* __restrict__ hc,
    const float* __restrict__ wm, const float* __restrict__ bm, float* __restrict__ mc)
{
    int bi = blockIdx.x;
    int sp = bi & 1; bi >>= 1;
    int g  = bi % 56;
    int b  = bi / 56;
    const float* in; const float* w; const float* bias; float* out; int co0; int cotot;
    if (g < 28)      { in = xin;  w = wx; bias = bx; out = xc; co0 = g * 16;        cotot = 448; }
    else if (g < 44) { in = hin;  w = wh; bias = bh; out = hc; co0 = (g - 28) * 16; cotot = 256; }
    else             { in = minb; w = wm; bias = bm; out = mc; co0 = (g - 44) * 16; cotot = 192; }
    conv_body<64, 2, 0>(in + (size_t)b * 64 * NPX, w, bias,
                        out + (size_t)b * cotot * NPX, co0, sp);
}

// ---- Wo conv: CI=128, CO=64, 4-way spatial split: grid = 8*4*4 = 128 ----
__global__ __launch_bounds__(128) void conv_oc_k(
    const float* __restrict__ mem, const float* __restrict__ wo,
    const float* __restrict__ bo, float* __restrict__ oc)
{
    int bi = blockIdx.x;
    int sp  = bi & 3;
    int cog = (bi >> 2) & 3;
    int b   = bi >> 4;
    conv_body<128, 4, 0>(mem + (size_t)b * 128 * NPX, wo, bo,
                         oc + (size_t)b * 64 * NPX, cog * 16, sp);
}

// ---- decoder conv: 152 images * 4 cog * 2 sp = 1216 blocks ----
__global__ __launch_bounds__(128) void conv_dec_k(
    const float* __restrict__ outs, const float* __restrict__ wd,
    const float* __restrict__ bd, float* __restrict__ dout)
{
    int bi = blockIdx.x;
    int sp  = bi & 1;
    int cog = (bi >> 1) & 3;
    int img = bi >> 3;          // 0..151, img = t*8 + b
    int t = img >> 3, b = img & 7;
    conv_body<64, 2, 1>(outs + (size_t)img * 64 * NPX, wd, bd,
                        dout + (size_t)(b * TT + t) * 65536, cog * 16, sp);
}

// ---- Wl 1x1 conv: grid = 8*4*2 = 64 blocks ----
__global__ __launch_bounds__(128) void conv1x1_k(
    const float* __restrict__ in, const float* __restrict__ w,
    const float* __restrict__ bias, float* __restrict__ out)
{
    __shared__ float s_w[16][128];
    int bi = blockIdx.x;
    int sp  = bi & 1;
    int cog = (bi >> 1) & 3;
    int b   = bi >> 3;
    int co0 = cog * 16;
    int tid = threadIdx.x;
    for (int i = tid; i < 16 * 128; i += 128) {
        int cc = i >> 7, ci = i & 127;
        s_w[cc][ci] = w[(co0 + cc) * 128 + ci];
    }
    __syncthreads();
    int cob = (tid >> 6) << 3;
    int pxg = tid & 63;
    const float* inb = in + (size_t)b * 128 * NPX + sp * 512 + pxg;
    float acc[8][8];
#pragma unroll
    for (int p = 0; p < 8; p++)
#pragma unroll
        for (int c2 = 0; c2 < 8; c2++) acc[p][c2] = bias[co0 + cob + c2];
#pragma unroll 1
    for (int ci = 0; ci < 128; ci++) {
        float wv[8];
#pragma unroll
        for (int c2 = 0; c2 < 8; c2++) wv[c2] = s_w[cob + c2][ci];
        const float* ip = inb + ci * NPX;
#pragma unroll
        for (int p = 0; p < 8; p++) {
            float iv = ip[64 * p];
#pragma unroll
            for (int c2 = 0; c2 < 8; c2++) acc[p][c2] = fmaf(iv, wv[c2], acc[p][c2]);
        }
    }
    float* ob = out + (size_t)b * 64 * NPX + sp * 512 + pxg;
#pragma unroll
    for (int p = 0; p < 8; p++)
#pragma unroll
        for (int c2 = 0; c2 < 8; c2++)
            ob[(co0 + cob + c2) * NPX + 64 * p] = acc[p][c2];
}

// ---- gate 1: i,f,g / i',f',g' -> c_new, m_new, mem ----
__global__ void gate1_k(const float* __restrict__ xc, const float* __restrict__ hc,
                        const float* __restrict__ mc, float* __restrict__ c,
                        float* __restrict__ m, float* __restrict__ mem)
{
    int idx = blockIdx.x * 256 + threadIdx.x;   // < 524288
    int px = idx & 1023;
    int ch = (idx >> 10) & 63;
    int b  = idx >> 16;
    const float* xcb = xc + (size_t)b * 448 * NPX;
    const float* hcb = hc + (size_t)b * 256 * NPX;
    const float* mcb = mc + (size_t)b * 192 * NPX;
    int o = ch * NPX + px;
    float ix  = xcb[o];              float fx  = xcb[o + 1 * 65536];
    float gx  = xcb[o + 2 * 65536];  float ixp = xcb[o + 3 * 65536];
    float fxp = xcb[o + 4 * 65536];  float gxp = xcb[o + 5 * 65536];
    float ih = hcb[o], fh = hcb[o + 65536], gh = hcb[o + 2 * 65536];
    float im = mcb[o], fm = mcb[o + 65536], gm = mcb[o + 2 * 65536];
    float it = sigf(ix + ih);
    float ft = sigf(fx + fh);
    float gt = tanhf(gx + gh);
    float cn = ft * c[idx] + it * gt;
    float itp = sigf(ixp + im);
    float ftp = sigf(fxp + fm);
    float gtp = tanhf(gxp + gm);
    float mn = ftp * m[idx] + itp * gtp;
    c[idx] = cn;
    m[idx] = mn;
    float* memb = mem + (size_t)b * 128 * NPX;
    memb[o]         = cn;
    memb[o + 65536] = mn;
}

// ---- gate 2: o_t, h_new ----
__global__ void gate2_k(const float* __restrict__ xc, const float* __restrict__ hc,
                        const float* __restrict__ oc, const float* __restrict__ lc,
                        float* __restrict__ h, float* __restrict__ out2)
{
    int idx = blockIdx.x * 256 + threadIdx.x;
    int px = idx & 1023;
    int ch = (idx >> 10) & 63;
    int b  = idx >> 16;
    int o  = ch * NPX + px;
    float ox = xc[(size_t)b * 448 * NPX + o + 6 * 65536];
    float oh = hc[(size_t)b * 256 * NPX + o + 3 * 65536];
    float ot = sigf(ox + oh + oc[idx]);
    float hv = ot * tanhf(lc[idx]);
    h[idx] = hv;
    if (out2) out2[idx] = hv;
}

// ---- patch (space-to-depth 8x8) ----
__global__ void patch_k(const float* __restrict__ x, float* __restrict__ xp)
{
    int idx = blockIdx.x * 256 + threadIdx.x;   // < 10*8*64*1024 = 5242880
    int px = idx & 1023;
    int ch = (idx >> 10) & 63;
    int b  = (idx >> 16) & 7;
    int t  = idx >> 19;
    int H = ((ch >> 3) << 5) + (px >> 5);
    int W = ((ch & 7) << 5) + (px & 31);
    xp[(size_t)(t * 8 + b) * 65536 + ch * NPX + px] =
        x[(size_t)(b * INLEN + t) * 65536 + H * 256 + W];
}

__global__ void zero_k(float* __restrict__ p, int n)
{
    int i = blockIdx.x * 256 + threadIdx.x;
    if (i < n) p[i] = 0.f;
}

// =====================================================================
extern "C" void kernel_launch(void* const* d_in, const int* in_sizes, int n_in,
                              void* d_out, int out_size)
{
    const float* x  = (const float*)d_in[0];
    const float* Wx = (const float*)d_in[3];
    const float* bx = (const float*)d_in[4];
    const float* Wh = (const float*)d_in[5];
    const float* bh = (const float*)d_in[6];
    const float* Wm = (const float*)d_in[7];
    const float* bm = (const float*)d_in[8];
    const float* Wo = (const float*)d_in[9];
    const float* bo = (const float*)d_in[10];
    const float* Wl = (const float*)d_in[11];
    const float* bl = (const float*)d_in[12];
    const float* Wd = (const float*)d_in[13];
    const float* bd = (const float*)d_in[14];
    float* out = (float*)d_out;

    float *xp, *h, *c, *m, *mem, *xc, *hc, *mc, *oc, *lc, *outs;
    cudaGetSymbolAddress((void**)&xp,   g_xp);
    cudaGetSymbolAddress((void**)&h,    g_h);
    cudaGetSymbolAddress((void**)&c,    g_c);
    cudaGetSymbolAddress((void**)&m,    g_m);
    cudaGetSymbolAddress((void**)&mem,  g_mem);
    cudaGetSymbolAddress((void**)&xc,   g_xc);
    cudaGetSymbolAddress((void**)&hc,   g_hc);
    cudaGetSymbolAddress((void**)&mc,   g_mc);
    cudaGetSymbolAddress((void**)&oc,   g_oc);
    cudaGetSymbolAddress((void**)&lc,   g_lc);
    cudaGetSymbolAddress((void**)&outs, g_outs);

    // zero states
    zero_k<<<(NLAY * LS + 255) / 256, 256>>>(h, NLAY * LS);
    zero_k<<<(NLAY * LS + 255) / 256, 256>>>(c, NLAY * LS);
    zero_k<<<(LS + 255) / 256, 256>>>(m, LS);

    // patch division
    patch_k<<<(INLEN * LS) / 256, 256>>>(x, xp);

    for (int t = 0; t < TT; t++) {
        const float* cur = (t < INLEN) ? (xp + (size_t)t * LS)
                                       : (outs + (size_t)(t - 1) * LS);
        for (int l = 0; l < NLAY; l++) {
            const float* inx = (l == 0) ? cur : (h + (size_t)(l - 1) * LS);
            conv_xhm_k<<<8 * 56 * 2, 128>>>(
                inx, h + (size_t)l * LS, m,
                Wx + (size_t)l * 448 * 64 * 9, bx + l * 448, xc,
                Wh + (size_t)l * 256 * 64 * 9, bh + l * 256, hc,
                Wm + (size_t)l * 192 * 64 * 9, bm + l * 192, mc);
            gate1_k<<<2048, 256>>>(xc, hc, mc, c + (size_t)l * LS, m, mem);
            conv_oc_k<<<8 * 4 * 4, 128>>>(mem, Wo + (size_t)l * 64 * 128 * 9,
                                          bo + l * 64, oc);
            conv1x1_k<<<8 * 4 * 2, 128>>>(mem, Wl + (size_t)l * 64 * 128,
                                          bl + l * 64, lc);
            gate2_k<<<2048, 256>>>(xc, hc, oc, lc, h + (size_t)l * LS,
                                   (l == 3) ? (outs + (size_t)t * LS) : nullptr);
        }
    }

    // decoder conv + sigmoid + depth-to-space
    conv_dec_k<<<152 * 4 * 2, 128>>>(outs, Wd, bd, out);
}

// round 6
// speedup vs baseline: 3.3607x; 3.3607x over previous
#include <cuda_runtime.h>
#include <cuda_bf16.h>
#include <math.h>
#include <stdint.h>

#define TT    19
#define INLEN 10
#define GPX   8192
#define LS    (GPX*64)
typedef __nv_bfloat16 bf;

// ---------------- device scratch ----------------
__device__ __align__(16) bf g_xh[INLEN*LS], g_xl[INLEN*LS];
__device__ __align__(16) bf g_hh[4*LS],     g_hl[4*LS];
__device__ __align__(16) bf g_mh[LS],       g_ml[LS];
__device__ __align__(16) bf g_memh[GPX*128], g_meml[GPX*128];
__device__ __align__(16) bf g_oth[TT*LS],   g_otl[TT*LS];
__device__ float g_c[4*LS];
__device__ float g_m[LS];
__device__ float g_xhm[(size_t)GPX*896];
__device__ __align__(16) bf g_W1[(size_t)4*14*18*4096];
__device__ __align__(16) bf g_W2[(size_t)4*36*8192];
__device__ __align__(16) bf g_W3[18*4096];
__device__ float g_b1[4*896], g_b2[4*128];

// ---------------- helpers ----------------
__device__ __forceinline__ uint32_t smem_u32(const void* p) {
    uint32_t a;
    asm("{ .reg .u64 t; cvta.to.shared.u64 t, %1; cvt.u32.u64 %0, t; }" : "=r"(a) : "l"(p));
    return a;
}
__device__ __forceinline__ float sigf(float v) { return 1.0f / (1.0f + expf(-v)); }
__device__ __forceinline__ void cpa16(uint32_t d, const void* s, uint32_t srcsz) {
    asm volatile("cp.async.cg.shared.global [%0], [%1], 16, %2;" :: "r"(d), "l"(s), "r"(srcsz));
}
__device__ __forceinline__ void cpa_commit() { asm volatile("cp.async.commit_group;" ::: "memory"); }
template<int N>
__device__ __forceinline__ void cpa_wait() { asm volatile("cp.async.wait_group %0;" :: "n"(N) : "memory"); }
__device__ __forceinline__ void ldm4(uint32_t* r, uint32_t a) {
    asm volatile("ldmatrix.sync.aligned.m8n8.x4.shared.b16 {%0,%1,%2,%3}, [%4];"
        : "=r"(r[0]), "=r"(r[1]), "=r"(r[2]), "=r"(r[3]) : "r"(a));
}
__device__ __forceinline__ void mma16816(float* d, const uint32_t* a, const uint32_t* b) {
    asm volatile("mma.sync.aligned.m16n8k16.row.col.f32.bf16.bf16.f32 "
        "{%0,%1,%2,%3}, {%4,%5,%6,%7}, {%8,%9}, {%0,%1,%2,%3};"
        : "+f"(d[0]), "+f"(d[1]), "+f"(d[2]), "+f"(d[3])
        : "r"(a[0]), "r"(a[1]), "r"(a[2]), "r"(a[3]), "r"(b[0]), "r"(b[1]));
}
template<int COT>
__device__ __forceinline__ void stageW(const bf* W, uint32_t Wb, int c, int tid) {
    const char* ws = (const char*)(W + (size_t)c * COT * 64);
    const uint32_t wb = Wb + (uint32_t)(c & 1) * 2 * (COT * 80);
    for (int i = tid; i < COT * 8; i += 256) {
        const int pl = i >= COT * 4;
        const int j  = i - pl * COT * 4;
        const int r = j >> 2, sg = j & 3;
        cpa16(wb + pl * (COT * 80) + r * 80 + sg * 16,
              ws + pl * COT * 64 + r * 64 + sg * 16, 16);
    }
}

// =====================================================================
// bf16x3 implicit-GEMM conv via mma.sync.
// Halo-resident activation tile (reused by all 9 taps), cp.async-double-
// buffered weight stream.  EPI 0: xhm store  EPI 1: fused gate2  EPI 2: decoder
// =====================================================================
template<int CIW, int COT, int PXT, int EPI>
__global__ void __launch_bounds__(256) gemm_k(
    const bf* __restrict__ xH, const bf* __restrict__ xL,
    const bf* __restrict__ hH, const bf* __restrict__ hL,
    const bf* __restrict__ mH, const bf* __restrict__ mL,
    const bf* __restrict__ Wg, const float* __restrict__ bias,
    float* __restrict__ xhm,
    bf* __restrict__ o0h, bf* __restrict__ o0l,
    bf* __restrict__ o1h, bf* __restrict__ o1l,
    float* __restrict__ dec)
{
    constexpr int NCH    = 9 * CIW / 32;
    constexpr int CPT    = CIW / 32;
    constexpr int APITCH = CIW * 2 + 16;
    constexpr int SROWS  = (PXT / 32 + 2) * 34;
    constexpr int APLANE = SROWS * APITCH;
    constexpr int WPLANE = COT * 80;
    constexpr int SEGS   = CIW / 8;

    extern __shared__ char smem[];
    const int tid = threadIdx.x, wid = tid >> 5, lane = tid & 31;
    const uint32_t sb = smem_u32(smem);
    const uint32_t Wb = sb + 2 * APLANE;

    const int mt = blockIdx.y;
    const bf *srcH, *srcL;
    if (EPI == 0) {
        if (mt < 7)       { srcH = xH; srcL = xL; }
        else if (mt < 11) { srcH = hH; srcL = hL; }
        else              { srcH = mH; srcL = mL; }
    } else { srcH = xH; srcL = xL; }
    const bf* W = Wg + (size_t)mt * NCH * COT * 64;

    const int px0 = blockIdx.x * PXT;
    const int img = px0 >> 10;
    const int y0  = (px0 & 1023) >> 5;

    // ---- stage A (once, halo, zero-filled borders) ----
    for (int i = tid; i < SROWS * SEGS; i += 256) {
        const int s = i / SEGS, seg = i % SEGS;
        const int yy = y0 + s / 34 - 1, xx = s % 34 - 1;
        const bool v = ((unsigned)yy < 32u) && ((unsigned)xx < 32u);
        const size_t off = v ? ((size_t)((img << 10) + yy * 32 + xx) * CIW + seg * 8) * 2 : 0;
        const uint32_t sz = v ? 16u : 0u;
        const uint32_t d = sb + (uint32_t)s * APITCH + seg * 16;
        cpa16(d,          (const char*)srcH + off, sz);
        cpa16(d + APLANE, (const char*)srcL + off, sz);
    }
    stageW<COT>(W, Wb, 0, tid);
    cpa_commit();

    // ---- warp geometry ----
    int wco, wpx;
    if (COT == 64) { wco = wid & 1; wpx = wid >> 1; }
    else           { wco = wid & 3; wpx = wid >> 2; }
    const int arow = lane & 15, ahalf = lane >> 4;
    const int brow = (lane & 7) + ((lane >> 4) << 3);
    const int bhalf = (lane >> 3) & 1;

    float acc[2][4][4] = {};

    for (int c = 0; c < NCH; c++) {
        if (c + 1 < NCH) { stageW<COT>(W, Wb, c + 1, tid); cpa_commit(); cpa_wait<1>(); }
        else             { cpa_wait<0>(); }
        __syncthreads();

        const int tap = c / CPT, ci0 = (c % CPT) * 32;
        const int dy = tap / 3 - 1, dx = tap % 3 - 1;
        const uint32_t abase = sb + (uint32_t)((wpx + 1 + dy) * 34 + 1 + dx) * APITCH + ci0 * 2;
        const uint32_t wbase = Wb + (uint32_t)(c & 1) * 2 * WPLANE + (uint32_t)(wco * 32) * 80;

#pragma unroll
        for (int kf = 0; kf < 2; kf++) {
            uint32_t wh_[2][4], wl_[2][4];
#pragma unroll
            for (int mf = 0; mf < 2; mf++) {
                const uint32_t ad = wbase + (uint32_t)(mf * 16 + arow) * 80 + kf * 32 + ahalf * 16;
                ldm4(wh_[mf], ad);
                ldm4(wl_[mf], ad + WPLANE);
            }
            uint32_t bh_[2][4], bl_[2][4];
#pragma unroll
            for (int nf = 0; nf < 2; nf++) {
                const uint32_t ad = abase + (uint32_t)(nf * 16 + brow) * APITCH + kf * 32 + bhalf * 16;
                ldm4(bh_[nf], ad);
                ldm4(bl_[nf], ad + APLANE);
            }
#pragma unroll
            for (int mf = 0; mf < 2; mf++)
#pragma unroll
                for (int n4 = 0; n4 < 4; n4++) {
                    const uint32_t* Bh = &bh_[n4 >> 1][(n4 & 1) * 2];
                    const uint32_t* Bl = &bl_[n4 >> 1][(n4 & 1) * 2];
                    mma16816(acc[mf][n4], wh_[mf], Bh);
                    mma16816(acc[mf][n4], wh_[mf], Bl);
                    mma16816(acc[mf][n4], wl_[mf], Bh);
                }
        }
        __syncthreads();
    }

    // ---- transpose accumulators into SMEM ----
    float* Dt = (float*)smem;
    constexpr int P = (EPI == 1) ? 132 : 68;
    __syncthreads();
#pragma unroll
    for (int mf = 0; mf < 2; mf++)
#pragma unroll
        for (int n4 = 0; n4 < 4; n4++) {
            const int row = wco * 32 + mf * 16 + (lane >> 2);
            const int col = wpx * 32 + n4 * 8 + (lane & 3) * 2;
            Dt[col * P + row]           = acc[mf][n4][0];
            Dt[(col + 1) * P + row]     = acc[mf][n4][1];
            Dt[col * P + row + 8]       = acc[mf][n4][2];
            Dt[(col + 1) * P + row + 8] = acc[mf][n4][3];
        }
    __syncthreads();

    if (EPI == 0) {
        const int coG = mt * 64;
        for (int i = tid * 4; i < PXT * 64; i += 1024) {
            const int px = i >> 6, co = i & 63;
            float4 v = *(const float4*)&Dt[px * 68 + co];
            v.x += bias[coG + co];     v.y += bias[coG + co + 1];
            v.z += bias[coG + co + 2]; v.w += bias[coG + co + 3];
            *(float4*)&xhm[(size_t)(px0 + px) * 896 + coG + co] = v;
        }
    } else if (EPI == 1) {
        for (int i = tid; i < 64 * 64; i += 256) {
            const int px = i >> 6, ch = i & 63;
            const size_t g = (size_t)(px0 + px);
            const float oc = Dt[px * 132 + ch] + bias[ch];
            const float lc = Dt[px * 132 + 64 + ch] + bias[64 + ch];
            const float ot = sigf(oc + xhm[g * 896 + 384 + ch] + xhm[g * 896 + 640 + ch]);
            const float hv = ot * tanhf(lc);
            const bf hi = __float2bfloat16(hv);
            const bf lo = __float2bfloat16(hv - __bfloat162float(hi));
            o0h[g * 64 + ch] = hi; o0l[g * 64 + ch] = lo;
            if (o1h) { o1h[g * 64 + ch] = hi; o1l[g * 64 + ch] = lo; }
        }
    } else {
        const int t = px0 >> 13, b = (px0 >> 10) & 7;
        const size_t obase = (size_t)(b * TT + t) * 65536;
        for (int j = tid; j < 8192; j += 256) {
            const int xx = j & 31, yy = (j >> 5) & 3, ch = j >> 7;
            const float v = sigf(Dt[(yy * 32 + xx) * 68 + ch] + bias[ch]);
            dec[obase + (size_t)((ch >> 3) * 32 + y0 + yy) * 256 + (ch & 7) * 32 + xx] = v;
        }
    }
}

// ---------------- gate 1 ----------------
__global__ void gate1_k(const float* __restrict__ xhm, float* __restrict__ c,
                        float* __restrict__ m, bf* __restrict__ memh,
                        bf* __restrict__ meml, bf* __restrict__ mh,
                        bf* __restrict__ ml)
{
    const int idx = blockIdx.x * 256 + threadIdx.x;
    const int px = idx >> 6, ch = idx & 63;
    const float* v = xhm + (size_t)px * 896;
    const float it  = sigf(v[ch]        + v[448 + ch]);
    const float ft  = sigf(v[64 + ch]   + v[512 + ch]);
    const float gt  = tanhf(v[128 + ch] + v[576 + ch]);
    const float cn  = ft * c[idx] + it * gt;
    const float itp = sigf(v[192 + ch]  + v[704 + ch]);
    const float ftp = sigf(v[256 + ch]  + v[768 + ch]);
    const float gtp = tanhf(v[320 + ch] + v[832 + ch]);
    const float mn  = ftp * m[idx] + itp * gtp;
    c[idx] = cn; m[idx] = mn;
    const bf chi = __float2bfloat16(cn);
    const bf mhi = __float2bfloat16(mn);
    memh[(size_t)px * 128 + ch]      = chi;
    memh[(size_t)px * 128 + 64 + ch] = mhi;
    meml[(size_t)px * 128 + ch]      = __float2bfloat16(cn - __bfloat162float(chi));
    meml[(size_t)px * 128 + 64 + ch] = __float2bfloat16(mn - __bfloat162float(mhi));
    mh[idx] = mhi;
    ml[idx] = __float2bfloat16(mn - __bfloat162float(mhi));
}

// ---------------- patch (space-to-depth, NHWC, bf16 split) ----------------
__global__ void patch_k(const float* __restrict__ x, bf* __restrict__ xh,
                        bf* __restrict__ xl)
{
    const int idx = blockIdx.x * 256 + threadIdx.x;
    const int ch = idx & 63, yx = (idx >> 6) & 1023;
    const int b = (idx >> 16) & 7, t = idx >> 19;
    const float v = x[(size_t)(b * INLEN + t) * 65536 +
                      (size_t)((ch >> 3) * 32 + (yx >> 5)) * 256 + (ch & 7) * 32 + (yx & 31)];
    const bf hi = __float2bfloat16(v);
    xh[idx] = hi;
    xl[idx] = __float2bfloat16(v - __bfloat162float(hi));
}

__global__ void zero_f(float* __restrict__ p, int n)
{
    const int i = blockIdx.x * 256 + threadIdx.x;
    if (i < n) p[i] = 0.f;
}

// ---------------- weight prep ----------------
__global__ void prepW1_k(const float* __restrict__ Wx, const float* __restrict__ Wh,
                         const float* __restrict__ Wm, bf* __restrict__ dst)
{
    const int idx = blockIdx.x * 256 + threadIdx.x;
    const int kk = idx & 31, row = (idx >> 5) & 63;
    const int c = (idx >> 11) % 18, r2 = (idx >> 11) / 18;
    const int mt = r2 % 14, l = r2 / 14;
    const int co = mt * 64 + row, tap = c >> 1, ci = ((c & 1) << 5) + kk;
    float v;
    if (co < 448)      v = Wx[((size_t)(l * 448 + co) * 64 + ci) * 9 + tap];
    else if (co < 704) v = Wh[((size_t)(l * 256 + co - 448) * 64 + ci) * 9 + tap];
    else               v = Wm[((size_t)(l * 192 + co - 704) * 64 + ci) * 9 + tap];
    const bf hi = __float2bfloat16(v);
    const size_t base = ((size_t)(l * 14 + mt) * 18 + c) * 4096;
    dst[base + row * 32 + kk]        = hi;
    dst[base + 2048 + row * 32 + kk] = __float2bfloat16(v - __bfloat162float(hi));
}

__global__ void prepW2_k(const float* __restrict__ Wo, const float* __restrict__ Wl,
                         bf* __restrict__ dst)
{
    const int idx = blockIdx.x * 256 + threadIdx.x;   // 4*36*4096 positions
    const int kk = idx & 31, row = (idx >> 5) & 127;
    const int c = (idx >> 12) % 36, l = (idx >> 12) / 36;
    const int tap = c >> 2, ci = ((c & 3) << 5) + kk;
    float v = 0.f;
    if (row < 64)      v = Wo[((size_t)(l * 64 + row) * 128 + ci) * 9 + tap];
    else if (tap == 4) v = Wl[(size_t)(l * 64 + row - 64) * 128 + ci];
    const bf hi = __float2bfloat16(v);
    const size_t base = (size_t)(l * 36 + c) * 8192;
    dst[base + row * 32 + kk]        = hi;
    dst[base + 4096 + row * 32 + kk] = __float2bfloat16(v - __bfloat162float(hi));
}

__global__ void prepW3_k(const float* __restrict__ Wd, bf* __restrict__ dst)
{
    const int idx = blockIdx.x * 256 + threadIdx.x;
    const int kk = idx & 31, row = (idx >> 5) & 63, c = idx >> 11;
    const int tap = c >> 1, ci = ((c & 1) << 5) + kk;
    const float v = Wd[((size_t)row * 64 + ci) * 9 + tap];
    const bf hi = __float2bfloat16(v);
    const size_t base = (size_t)c * 4096;
    dst[base + row * 32 + kk]        = hi;
    dst[base + 2048 + row * 32 + kk] = __float2bfloat16(v - __bfloat162float(hi));
}

__global__ void prepb_k(const float* __restrict__ bx, const float* __restrict__ bh,
                        const float* __restrict__ bm, const float* __restrict__ bo,
                        const float* __restrict__ bl, float* __restrict__ b1,
                        float* __restrict__ b2)
{
    const int idx = blockIdx.x * 256 + threadIdx.x;
    if (idx < 4 * 896) {
        const int l = idx / 896, j = idx % 896;
        b1[idx] = j < 448 ? bx[l * 448 + j]
                : j < 704 ? bh[l * 256 + j - 448]
                          : bm[l * 192 + j - 704];
    } else if (idx < 4096) {
        const int k = idx - 3584, l = k / 128, j = k % 128;
        b2[k] = j < 64 ? bo[l * 64 + j] : bl[l * 64 + j - 64];
    }
}

// =====================================================================
extern "C" void kernel_launch(void* const* d_in, const int* in_sizes, int n_in,
                              void* d_out, int out_size)
{
    const float* x  = (const float*)d_in[0];
    const float* Wx = (const float*)d_in[3];
    const float* bx = (const float*)d_in[4];
    const float* Wh = (const float*)d_in[5];
    const float* bh = (const float*)d_in[6];
    const float* Wm = (const float*)d_in[7];
    const float* bm = (const float*)d_in[8];
    const float* Wo = (const float*)d_in[9];
    const float* bo = (const float*)d_in[10];
    const float* Wl = (const float*)d_in[11];
    const float* bl = (const float*)d_in[12];
    const float* Wd = (const float*)d_in[13];
    const float* bd = (const float*)d_in[14];
    float* out = (float*)d_out;

    bf *xh, *xl, *hh, *hl, *mh, *ml, *memh, *meml, *oth, *otl, *W1, *W2, *W3;
    float *c, *m, *xhm, *b1, *b2;
    cudaGetSymbolAddress((void**)&xh,   g_xh);
    cudaGetSymbolAddress((void**)&xl,   g_xl);
    cudaGetSymbolAddress((void**)&hh,   g_hh);
    cudaGetSymbolAddress((void**)&hl,   g_hl);
    cudaGetSymbolAddress((void**)&mh,   g_mh);
    cudaGetSymbolAddress((void**)&ml,   g_ml);
    cudaGetSymbolAddress((void**)&memh, g_memh);
    cudaGetSymbolAddress((void**)&meml, g_meml);
    cudaGetSymbolAddress((void**)&oth,  g_oth);
    cudaGetSymbolAddress((void**)&otl,  g_otl);
    cudaGetSymbolAddress((void**)&c,    g_c);
    cudaGetSymbolAddress((void**)&m,    g_m);
    cudaGetSymbolAddress((void**)&xhm,  g_xhm);
    cudaGetSymbolAddress((void**)&W1,   g_W1);
    cudaGetSymbolAddress((void**)&W2,   g_W2);
    cudaGetSymbolAddress((void**)&W3,   g_W3);
    cudaGetSymbolAddress((void**)&b1,   g_b1);
    cudaGetSymbolAddress((void**)&b2,   g_b2);

    const int G1SM = 2 * (204 * 144) + 4 * (64 * 80);    // 79232
    const int G2SM = 2 * (136 * 272) + 4 * (128 * 80);   // 114944
    cudaFuncSetAttribute(gemm_k<64, 64, 128, 0>,
                         cudaFuncAttributeMaxDynamicSharedMemorySize, G1SM);
    cudaFuncSetAttribute(gemm_k<128, 128, 64, 1>,
                         cudaFuncAttributeMaxDynamicSharedMemorySize, G2SM);
    cudaFuncSetAttribute(gemm_k<64, 64, 128, 2>,
                         cudaFuncAttributeMaxDynamicSharedMemorySize, G1SM);

    // zero states
    zero_f<<<((2 * LS) + 255) / 256, 256>>>((float*)hh, 2 * LS);
    zero_f<<<((2 * LS) + 255) / 256, 256>>>((float*)hl, 2 * LS);
    zero_f<<<((LS / 2) + 255) / 256, 256>>>((float*)mh, LS / 2);
    zero_f<<<((LS / 2) + 255) / 256, 256>>>((float*)ml, LS / 2);
    zero_f<<<(4 * LS + 255) / 256, 256>>>(c, 4 * LS);
    zero_f<<<(LS + 255) / 256, 256>>>(m, LS);

    patch_k<<<(INLEN * LS) / 256, 256>>>(x, xh, xl);
    prepW1_k<<<8064, 256>>>(Wx, Wh, Wm, W1);
    prepW2_k<<<2304, 256>>>(Wo, Wl, W2);      // FIXED: was 4608 (OOB writes)
    prepW3_k<<<144, 256>>>(Wd, W3);
    prepb_k<<<16, 256>>>(bx, bh, bm, bo, bl, b1, b2);

    for (int t = 0; t < TT; t++) {
        const bf* curh = (t < INLEN) ? (xh + (size_t)t * LS) : (oth + (size_t)(t - 1) * LS);
        const bf* curl = (t < INLEN) ? (xl + (size_t)t * LS) : (otl + (size_t)(t - 1) * LS);
        for (int l = 0; l < 4; l++) {
            const bf* inh = (l == 0) ? curh : (hh + (size_t)(l - 1) * LS);
            const bf* inl = (l == 0) ? curl : (hl + (size_t)(l - 1) * LS);
            gemm_k<64, 64, 128, 0><<<dim3(64, 14), 256, G1SM>>>(
                inh, inl, hh + (size_t)l * LS, hl + (size_t)l * LS, mh, ml,
                W1 + (size_t)l * 14 * 18 * 4096, b1 + l * 896, xhm,
                nullptr, nullptr, nullptr, nullptr, nullptr);
            gate1_k<<<2048, 256>>>(xhm, c + (size_t)l * LS, m, memh, meml, mh, ml);
            gemm_k<128, 128, 64, 1><<<dim3(128, 1), 256, G2SM>>>(
                memh, meml, nullptr, nullptr, nullptr, nullptr,
                W2 + (size_t)l * 36 * 8192, b2 + l * 128, xhm,
                hh + (size_t)l * LS, hl + (size_t)l * LS,
                (l == 3) ? (oth + (size_t)t * LS) : nullptr,
                (l == 3) ? (otl + (size_t)t * LS) : nullptr, nullptr);
        }
    }

    gemm_k<64, 64, 128, 2><<<dim3(1216, 1), 256, G1SM>>>(
        oth, otl, nullptr, nullptr, nullptr, nullptr,
        W3, bd, nullptr, nullptr, nullptr, nullptr, nullptr, out);
}